// round 2
// baseline (speedup 1.0000x reference)
#include <cuda_runtime.h>

// Problem constants
#define Nn   8
#define Cc   64
#define Hh   128
#define Ww   128
#define Oo   64
#define HW   (Hh*Ww)          // 16384
#define Kk   9
#define CKt  576              // C*K
#define TPt  32               // positions per tile
#define CKC  72               // ck per weight chunk (8 channels)
#define WPAD 73               // padded wsm row stride (bank-conflict-free)

// dynamic smem layout (bytes)
#define SMEM_S    0                       // s[576][32] floats     = 73728
#define SMEM_W    73728                   // wsm[64][73] floats    = 18688
#define SMEM_IDX  92416                   // int4  sidx[288]       = 4608
#define SMEM_WGT  97024                   // float4 sw[288]        = 4608
#define SMEM_TOTAL 101632

__device__ __forceinline__ void fma2(unsigned long long &d,
                                     unsigned long long a,
                                     unsigned long long b) {
    asm("fma.rn.f32x2 %0, %1, %2, %0;" : "+l"(d) : "l"(a), "l"(b));
}
__device__ __forceinline__ unsigned long long splat2(float v) {
    unsigned long long r;
    asm("mov.b64 %0, {%1, %2};" : "=l"(r) : "f"(v), "f"(v));
    return r;
}
__device__ __forceinline__ float2 unpack2(unsigned long long v) {
    float2 f;
    asm("mov.b64 {%0, %1}, %2;" : "=f"(f.x), "=f"(f.y) : "l"(v));
    return f;
}

__global__ __launch_bounds__(256, 2)
void deform_conv_kernel(const float* __restrict__ x,
                        const float* __restrict__ offset,
                        const float* __restrict__ weight,
                        float* __restrict__ out)
{
    extern __shared__ char smem[];
    float*  s    = (float*) (smem + SMEM_S);
    float*  wsm  = (float*) (smem + SMEM_W);
    int4*   sidx = (int4*)  (smem + SMEM_IDX);
    float4* sw   = (float4*)(smem + SMEM_WGT);

    const int tid = threadIdx.x;
    const int b   = blockIdx.x;
    const int n   = b >> 9;          // 512 tiles per image
    const int rem = b & 511;
    const int ho  = rem >> 2;        // 4 tiles per output row
    const int wo0 = (rem & 3) << 5;  // tile start column

    // ---------------- Phase A: sampling metadata per (k, p) -----------------
    for (int kp = tid; kp < Kk * TPt; kp += 256) {
        int k  = kp >> 5;
        int p  = kp & 31;
        int kh = k / 3, kw = k - 3 * kh;
        int wo = wo0 + p;
        const float* offp = offset + ((size_t)n * 18 + 2 * k) * HW + ho * Ww + wo;
        float oy = __ldg(offp);
        float ox = __ldg(offp + HW);
        float py = (float)(ho - 1 + kh) + oy;
        float px = (float)(wo - 1 + kw) + ox;
        // keep int conversion well-defined for pathological offsets
        py = fminf(fmaxf(py, -16384.f), 16384.f);
        px = fminf(fmaxf(px, -16384.f), 16384.f);
        float y0f = floorf(py), x0f = floorf(px);
        float wy = py - y0f, wx = px - x0f;
        int y0 = (int)y0f, x0 = (int)x0f;
        int y1 = y0 + 1,   x1 = x0 + 1;
        float vy0 = (y0 >= 0 && y0 < Hh) ? 1.f : 0.f;
        float vy1 = (y1 >= 0 && y1 < Hh) ? 1.f : 0.f;
        float vx0 = (x0 >= 0 && x0 < Ww) ? 1.f : 0.f;
        float vx1 = (x1 >= 0 && x1 < Ww) ? 1.f : 0.f;
        int cy0 = min(max(y0, 0), Hh - 1), cy1 = min(max(y1, 0), Hh - 1);
        int cx0 = min(max(x0, 0), Ww - 1), cx1 = min(max(x1, 0), Ww - 1);
        sw[kp]   = make_float4((1.f - wy) * (1.f - wx) * vy0 * vx0,
                               (1.f - wy) * wx         * vy0 * vx1,
                               wy         * (1.f - wx) * vy1 * vx0,
                               wy         * wx         * vy1 * vx1);
        sidx[kp] = make_int4(cy0 * Ww + cx0, cy0 * Ww + cx1,
                             cy1 * Ww + cx0, cy1 * Ww + cx1);
    }
    __syncthreads();

    // ---------------- Phase B: bilinear gather into s[ck][p] ----------------
    const int lane = tid & 31;
    const int wrp  = tid >> 5;
    for (int r = wrp; r < CKt; r += 8) {
        int c = r / 9, k = r - 9 * c;
        int4   id = sidx[(k << 5) + lane];
        float4 wv = sw  [(k << 5) + lane];
        const float* xp = x + (n * Cc + c) * HW;
        float v = wv.x * __ldg(xp + id.x) + wv.y * __ldg(xp + id.y)
                + wv.z * __ldg(xp + id.z) + wv.w * __ldg(xp + id.w);
        s[(r << 5) + lane] = v;
    }

    // ---------------- Phase C: GEMM  out[64][32] = W[64][576] * s[576][32] --
    // thread tile: 2 outputs (o0, o0+1) x 4 positions (p0..p0+3) as f32x2 pairs
    const int o0 = (tid >> 3) << 1;
    const int p0 = (tid & 7) << 2;
    unsigned long long a00 = 0, a01 = 0, a10 = 0, a11 = 0;

    for (int cc = 0; cc < 8; cc++) {
        __syncthreads();   // also orders Phase B writes on first iteration
        // stage weight chunk: wsm[o][j] = weight[o][cc*72 + j], padded stride
        for (int i = tid; i < Oo * CKC; i += 256) {
            int o = i / CKC, j = i - o * CKC;
            wsm[o * WPAD + j] = __ldg(weight + o * CKt + cc * CKC + j);
        }
        __syncthreads();
        const float* sb = s + cc * CKC * TPt;
        #pragma unroll 8
        for (int j = 0; j < CKC; j++) {
            ulonglong2 sv = *reinterpret_cast<const ulonglong2*>(sb + (j << 5) + p0);
            float w0 = wsm[o0 * WPAD + j];
            float w1 = wsm[o0 * WPAD + WPAD + j];
            unsigned long long wa = splat2(w0);
            unsigned long long wb = splat2(w1);
            fma2(a00, wa, sv.x); fma2(a01, wa, sv.y);
            fma2(a10, wb, sv.x); fma2(a11, wb, sv.y);
        }
    }

    // ---------------- epilogue ----------------
    float2 f00 = unpack2(a00), f01 = unpack2(a01);
    float2 f10 = unpack2(a10), f11 = unpack2(a11);
    float* op = out + ((n * Oo + o0) * Hh + ho) * Ww + wo0 + p0;
    *reinterpret_cast<float4*>(op)      = make_float4(f00.x, f00.y, f01.x, f01.y);
    *reinterpret_cast<float4*>(op + HW) = make_float4(f10.x, f10.y, f11.x, f11.y);
}

extern "C" void kernel_launch(void* const* d_in, const int* in_sizes, int n_in,
                              void* d_out, int out_size) {
    const float* x      = (const float*)d_in[0];
    const float* offset = (const float*)d_in[1];
    const float* weight = (const float*)d_in[2];
    float* out = (float*)d_out;
    (void)in_sizes; (void)n_in; (void)out_size;

    // Host-side one-time attribute set (host statics are allowed; only device
    // allocations are forbidden). Keeps non-stream runtime calls out of the
    // graph-captured replay path.
    static bool attr_set = false;
    if (!attr_set) {
        cudaFuncSetAttribute(deform_conv_kernel,
                             cudaFuncAttributeMaxDynamicSharedMemorySize, SMEM_TOTAL);
        attr_set = true;
    }
    deform_conv_kernel<<<Nn * 512, 256, SMEM_TOTAL>>>(x, offset, weight, out);
}

// round 8
// speedup vs baseline: 1.5310x; 1.5310x over previous
#include <cuda_runtime.h>
#include <cstdint>

// Problem constants
#define Nn   8
#define Cc   64
#define Hh   128
#define Ww   128
#define Oo   64
#define HW   16384
#define Kk   9
#define CKt  576
#define CHUNK 72          // ck rows per chunk (8 channels x 9 taps)
#define NCH   8           // number of chunks
#define TP    128         // positions per block = one output row
#define WPAD  73          // padded w row stride (floats)

// dynamic smem layout (floats)
#define SB0   0
#define SB1   (CHUNK*TP)                  // 9216
#define WB0   (2*CHUNK*TP)                // 18432
#define WB1   (2*CHUNK*TP + Oo*WPAD)      // 18432+4672
#define SMEM_FLOATS (2*CHUNK*TP + 2*Oo*WPAD)   // 27776 floats = 111104 B

__device__ __forceinline__ void fma2(unsigned long long &d,
                                     unsigned long long a,
                                     unsigned long long b) {
    asm("fma.rn.f32x2 %0, %1, %2, %0;" : "+l"(d) : "l"(a), "l"(b));
}
__device__ __forceinline__ unsigned long long splat2(float v) {
    unsigned long long r;
    asm("mov.b64 %0, {%1, %2};" : "=l"(r) : "f"(v), "f"(v));
    return r;
}
__device__ __forceinline__ float2 unpack2(unsigned long long v) {
    float2 f;
    asm("mov.b64 {%0, %1}, %2;" : "=f"(f.x), "=f"(f.y) : "l"(v));
    return f;
}

__global__ __launch_bounds__(256, 2)
void deform_conv_kernel(const float* __restrict__ x,
                        const float* __restrict__ offset,
                        const float* __restrict__ weight,
                        float* __restrict__ out)
{
    extern __shared__ float sm[];
    float* const sA = sm + SB0;
    float* const sB = sm + SB1;
    float* const wA = sm + WB0;
    float* const wB = sm + WB1;

    const int tid = threadIdx.x;
    const int b   = blockIdx.x;
    const int n   = b >> 7;          // 128 blocks per image
    const int ho  = b & 127;         // output row
    const int p   = tid & 127;       // this thread's gather column

    // ------------- Phase A: per-thread sampling metadata (registers) -------
    // Each thread gathers a fixed column p; only 9 (k) metas needed.
    float4   mw[Kk];
    uint32_t mi0[Kk], mi1[Kk];       // packed u16 byte offsets: (t00,t01),(t10,t11)
    #pragma unroll
    for (int k = 0; k < Kk; k++) {
        int kh = k / 3, kw = k - 3 * kh;
        const float* offp = offset + (size_t)(n * 18 + 2 * k) * HW + ho * Ww + p;
        float oy = __ldg(offp);
        float ox = __ldg(offp + HW);
        float py = (float)(ho - 1 + kh) + oy;
        float px = (float)(p  - 1 + kw) + ox;
        py = fminf(fmaxf(py, -16384.f), 16384.f);
        px = fminf(fmaxf(px, -16384.f), 16384.f);
        float y0f = floorf(py), x0f = floorf(px);
        float wy = py - y0f,    wx = px - x0f;
        int y0 = (int)y0f, x0 = (int)x0f;
        int y1 = y0 + 1,   x1 = x0 + 1;
        float vy0 = (y0 >= 0 && y0 < Hh) ? 1.f : 0.f;
        float vy1 = (y1 >= 0 && y1 < Hh) ? 1.f : 0.f;
        float vx0 = (x0 >= 0 && x0 < Ww) ? 1.f : 0.f;
        float vx1 = (x1 >= 0 && x1 < Ww) ? 1.f : 0.f;
        int cy0 = min(max(y0, 0), Hh - 1), cy1 = min(max(y1, 0), Hh - 1);
        int cx0 = min(max(x0, 0), Ww - 1), cx1 = min(max(x1, 0), Ww - 1);
        mw[k] = make_float4((1.f - wy) * (1.f - wx) * vy0 * vx0,
                            (1.f - wy) * wx         * vy0 * vx1,
                            wy         * (1.f - wx) * vy1 * vx0,
                            wy         * wx         * vy1 * vx1);
        uint32_t t00 = (uint32_t)((cy0 * Ww + cx0) << 2);
        uint32_t t01 = (uint32_t)((cy0 * Ww + cx1) << 2);
        uint32_t t10 = (uint32_t)((cy1 * Ww + cx0) << 2);
        uint32_t t11 = (uint32_t)((cy1 * Ww + cx1) << 2);
        mi0[k] = t00 | (t01 << 16);
        mi1[k] = t10 | (t11 << 16);
    }

    const char* const xb = (const char*)(x + (size_t)n * Cc * HW);
    const int r0 = tid >> 7;         // 0 or 1: even/odd rows

    // ------------- gather one chunk (72 rows x 128 p) into sb --------------
    auto gather = [&](int cc, float* __restrict__ sb) {
        int r = r0;
        #pragma unroll
        for (int i = 0; i < 36; i++, r += 2) {
            int cl = r / 9;
            int k  = r - cl * 9;
            const char* xp = xb + ((size_t)(cc * 8 + cl) * HW) * 4;
            uint32_t i0 = mi0[k], i1 = mi1[k];
            float4 w = mw[k];
            float v = w.x * *(const float*)(xp + (i0 & 0xFFFFu))
                    + w.y * *(const float*)(xp + (i0 >> 16))
                    + w.z * *(const float*)(xp + (i1 & 0xFFFFu))
                    + w.w * *(const float*)(xp + (i1 >> 16));
            sb[r * TP + p] = v;
        }
    };

    // ------------- stage one weight chunk: wb[o*73 + j] --------------------
    auto stagew = [&](int cc, float* __restrict__ wb) {
        const float* wsrc = weight + cc * CHUNK;
        #pragma unroll
        for (int i = tid; i < Oo * CHUNK; i += 256) {
            int o = i / CHUNK;
            int j = i - o * CHUNK;
            wb[o * WPAD + j] = __ldg(wsrc + o * CKt + j);
        }
    };

    // ------------- GEMM state: warp owns 8 o-rows, lane owns 4 p -----------
    const int owarp = (tid >> 5) << 3;     // 0,8,...,56
    const int p0    = (tid & 31) << 2;     // 0..124
    unsigned long long acc[8][2];
    #pragma unroll
    for (int m = 0; m < 8; m++) { acc[m][0] = 0ull; acc[m][1] = 0ull; }

    auto gemm = [&](const float* __restrict__ sb, const float* __restrict__ wb) {
        const float* wp = wb + owarp * WPAD;
        #pragma unroll 4
        for (int j = 0; j < CHUNK; j++) {
            ulonglong2 sv = *(const ulonglong2*)(sb + j * TP + p0);
            #pragma unroll
            for (int m = 0; m < 8; m++) {
                unsigned long long wv = splat2(wp[m * WPAD + j]);
                fma2(acc[m][0], wv, sv.x);
                fma2(acc[m][1], wv, sv.y);
            }
        }
    };

    // ------------- main pipeline: double-buffered chunks -------------------
    gather(0, sA);
    stagew(0, wA);
    __syncthreads();
    #pragma unroll 1
    for (int cc = 0; cc < NCH; cc++) {
        float* scur = (cc & 1) ? sB : sA;
        float* wcur = (cc & 1) ? wB : wA;
        if (cc < NCH - 1) {
            gather(cc + 1, (cc & 1) ? sA : sB);
            stagew(cc + 1, (cc & 1) ? wA : wB);
        }
        gemm(scur, wcur);
        __syncthreads();
    }

    // ------------- epilogue ------------------------------------------------
    float* ob = out + (size_t)(n * Oo + owarp) * HW + ho * Ww + p0;
    #pragma unroll
    for (int m = 0; m < 8; m++) {
        float2 lo = unpack2(acc[m][0]);
        float2 hi = unpack2(acc[m][1]);
        *(float4*)(ob + m * HW) = make_float4(lo.x, lo.y, hi.x, hi.y);
    }
}

extern "C" void kernel_launch(void* const* d_in, const int* in_sizes, int n_in,
                              void* d_out, int out_size) {
    const float* x      = (const float*)d_in[0];
    const float* offset = (const float*)d_in[1];
    const float* weight = (const float*)d_in[2];
    float* out = (float*)d_out;
    (void)in_sizes; (void)n_in; (void)out_size;

    static bool attr_set = false;
    if (!attr_set) {
        cudaFuncSetAttribute(deform_conv_kernel,
                             cudaFuncAttributeMaxDynamicSharedMemorySize,
                             SMEM_FLOATS * (int)sizeof(float));
        attr_set = true;
    }
    deform_conv_kernel<<<Nn * 128, 256, SMEM_FLOATS * sizeof(float)>>>(x, offset, weight, out);
}

// round 13
// speedup vs baseline: 1.6039x; 1.0476x over previous
#include <cuda_runtime.h>
#include <cstdint>

// Problem constants
#define Nn   8
#define Cc   64
#define Hh   128
#define Ww   128
#define Oo   64
#define HW   16384
#define Kk   9
#define CKt  576
#define CHUNK 72          // ck rows per chunk (8 channels x 9 taps)
#define NCH   8           // number of chunks
#define TP    128         // positions per block = one output row
#define WT    68          // transposed w row stride (floats, 16B-aligned)

// dynamic smem layout (floats)
#define SB0   0
#define SB1   (CHUNK*TP)                  // 9216
#define WB0   (2*CHUNK*TP)                // 18432
#define WB1   (2*CHUNK*TP + CHUNK*WT)     // +4896
#define SMEM_FLOATS (2*CHUNK*TP + 2*CHUNK*WT)  // 28224 floats = 112896 B

__device__ __forceinline__ void fma2(unsigned long long &d,
                                     unsigned long long a,
                                     unsigned long long b) {
    asm("fma.rn.f32x2 %0, %1, %2, %0;" : "+l"(d) : "l"(a), "l"(b));
}
__device__ __forceinline__ unsigned long long splat2(float v) {
    unsigned long long r;
    asm("mov.b64 %0, {%1, %2};" : "=l"(r) : "f"(v), "f"(v));
    return r;
}
__device__ __forceinline__ float2 unpack2(unsigned long long v) {
    float2 f;
    asm("mov.b64 {%0, %1}, %2;" : "=f"(f.x), "=f"(f.y) : "l"(v));
    return f;
}

__global__ __launch_bounds__(256, 2)
void deform_conv_kernel(const float* __restrict__ x,
                        const float* __restrict__ offset,
                        const float* __restrict__ weight,
                        float* __restrict__ out)
{
    extern __shared__ float sm[];
    float* const sA = sm + SB0;
    float* const sB = sm + SB1;
    float* const wA = sm + WB0;
    float* const wB = sm + WB1;

    const int tid = threadIdx.x;
    const int b   = blockIdx.x;
    const int n   = b >> 7;          // 128 blocks per image
    const int ho  = b & 127;         // output row
    const int p   = tid & 127;       // this thread's gather column

    // ------------- Phase A: per-thread sampling metadata (registers) -------
    float4   mw[Kk];
    uint32_t mi0[Kk], mi1[Kk];       // packed u16 byte offsets
    #pragma unroll
    for (int k = 0; k < Kk; k++) {
        int kh = k / 3, kw = k - 3 * kh;
        const float* offp = offset + (size_t)(n * 18 + 2 * k) * HW + ho * Ww + p;
        float oy = __ldg(offp);
        float ox = __ldg(offp + HW);
        float py = (float)(ho - 1 + kh) + oy;
        float px = (float)(p  - 1 + kw) + ox;
        py = fminf(fmaxf(py, -16384.f), 16384.f);
        px = fminf(fmaxf(px, -16384.f), 16384.f);
        float y0f = floorf(py), x0f = floorf(px);
        float wy = py - y0f,    wx = px - x0f;
        int y0 = (int)y0f, x0 = (int)x0f;
        int y1 = y0 + 1,   x1 = x0 + 1;
        float vy0 = (y0 >= 0 && y0 < Hh) ? 1.f : 0.f;
        float vy1 = (y1 >= 0 && y1 < Hh) ? 1.f : 0.f;
        float vx0 = (x0 >= 0 && x0 < Ww) ? 1.f : 0.f;
        float vx1 = (x1 >= 0 && x1 < Ww) ? 1.f : 0.f;
        int cy0 = min(max(y0, 0), Hh - 1), cy1 = min(max(y1, 0), Hh - 1);
        int cx0 = min(max(x0, 0), Ww - 1), cx1 = min(max(x1, 0), Ww - 1);
        mw[k] = make_float4((1.f - wy) * (1.f - wx) * vy0 * vx0,
                            (1.f - wy) * wx         * vy0 * vx1,
                            wy         * (1.f - wx) * vy1 * vx0,
                            wy         * wx         * vy1 * vx1);
        uint32_t t00 = (uint32_t)((cy0 * Ww + cx0) << 2);
        uint32_t t01 = (uint32_t)((cy0 * Ww + cx1) << 2);
        uint32_t t10 = (uint32_t)((cy1 * Ww + cx0) << 2);
        uint32_t t11 = (uint32_t)((cy1 * Ww + cx1) << 2);
        mi0[k] = t00 | (t01 << 16);
        mi1[k] = t10 | (t11 << 16);
    }

    const char* const xb = (const char*)(x + (size_t)n * Cc * HW);
    const int half = tid >> 7;       // 0/1: contiguous half of the 72 rows

    // ------------- gather one chunk (72 rows x 128 p) into sb --------------
    // rows r = half*36 + i; 36 % 9 == 0 so k = i % 9 is COMPILE-TIME under
    // full unroll -> metadata arrays stay in registers (no local memory).
    auto gather = [&](int cc, float* __restrict__ sb) {
        #pragma unroll
        for (int i = 0; i < 36; i++) {
            const int k  = i % 9;                 // compile-time
            const int cl = half * 4 + i / 9;      // channel within chunk
            const char* xp = xb + ((size_t)(cc * 8 + cl) * HW) * 4;
            uint32_t i0 = mi0[k], i1 = mi1[k];
            float4 w = mw[k];
            float v = w.x * *(const float*)(xp + (i0 & 0xFFFFu))
                    + w.y * *(const float*)(xp + (i0 >> 16))
                    + w.z * *(const float*)(xp + (i1 & 0xFFFFu))
                    + w.w * *(const float*)(xp + (i1 >> 16));
            sb[(half * 36 + i) * TP + p] = v;
        }
    };

    // ------------- stage one weight chunk TRANSPOSED: wb[j*WT + o] ---------
    auto stagew = [&](int cc, float* __restrict__ wb) {
        const float* wsrc = weight + cc * CHUNK;
        #pragma unroll
        for (int i = tid; i < Oo * CHUNK; i += 256) {
            int o = i / CHUNK;                 // coalesced read over j
            int j = i - o * CHUNK;
            wb[j * WT + o] = __ldg(wsrc + o * CKt + j);
        }
    };

    // ------------- GEMM: warp owns 8 o (as 4 pairs) x lane 4 p -------------
    const int o0 = (tid >> 5) << 3;     // 0,8,...,56
    const int p0 = (tid & 31) << 2;     // 0..124
    unsigned long long acc[4][4];       // [o-pair q][p idx]
    #pragma unroll
    for (int q = 0; q < 4; q++)
        #pragma unroll
        for (int pp = 0; pp < 4; pp++) acc[q][pp] = 0ull;

    auto gemm = [&](const float* __restrict__ sb, const float* __restrict__ wb) {
        #pragma unroll 4
        for (int j = 0; j < CHUNK; j++) {
            float4 s4 = *(const float4*)(sb + j * TP + p0);
            unsigned long long s0 = splat2(s4.x), s1 = splat2(s4.y);
            unsigned long long s2 = splat2(s4.z), s3 = splat2(s4.w);
            ulonglong2 wlo = *(const ulonglong2*)(wb + j * WT + o0);      // pairs q0,q1
            ulonglong2 whi = *(const ulonglong2*)(wb + j * WT + o0 + 4);  // pairs q2,q3
            fma2(acc[0][0], wlo.x, s0); fma2(acc[0][1], wlo.x, s1);
            fma2(acc[0][2], wlo.x, s2); fma2(acc[0][3], wlo.x, s3);
            fma2(acc[1][0], wlo.y, s0); fma2(acc[1][1], wlo.y, s1);
            fma2(acc[1][2], wlo.y, s2); fma2(acc[1][3], wlo.y, s3);
            fma2(acc[2][0], whi.x, s0); fma2(acc[2][1], whi.x, s1);
            fma2(acc[2][2], whi.x, s2); fma2(acc[2][3], whi.x, s3);
            fma2(acc[3][0], whi.y, s0); fma2(acc[3][1], whi.y, s1);
            fma2(acc[3][2], whi.y, s2); fma2(acc[3][3], whi.y, s3);
        }
    };

    // ------------- main pipeline: double-buffered chunks -------------------
    gather(0, sA);
    stagew(0, wA);
    __syncthreads();
    #pragma unroll 1
    for (int cc = 0; cc < NCH; cc++) {
        float* scur = (cc & 1) ? sB : sA;
        float* wcur = (cc & 1) ? wB : wA;
        if (cc < NCH - 1) {
            gather(cc + 1, (cc & 1) ? sA : sB);
            stagew(cc + 1, (cc & 1) ? wA : wB);
        }
        gemm(scur, wcur);
        __syncthreads();
    }

    // ------------- epilogue ------------------------------------------------
    // acc[q][pp] = (out[o0+2q][p0+pp], out[o0+2q+1][p0+pp])
    float* ob = out + (size_t)(n * Oo + o0) * HW + ho * Ww + p0;
    #pragma unroll
    for (int q = 0; q < 4; q++) {
        float2 v0 = unpack2(acc[q][0]);
        float2 v1 = unpack2(acc[q][1]);
        float2 v2 = unpack2(acc[q][2]);
        float2 v3 = unpack2(acc[q][3]);
        *(float4*)(ob + (2 * q)     * HW) = make_float4(v0.x, v1.x, v2.x, v3.x);
        *(float4*)(ob + (2 * q + 1) * HW) = make_float4(v0.y, v1.y, v2.y, v3.y);
    }
}

extern "C" void kernel_launch(void* const* d_in, const int* in_sizes, int n_in,
                              void* d_out, int out_size) {
    const float* x      = (const float*)d_in[0];
    const float* offset = (const float*)d_in[1];
    const float* weight = (const float*)d_in[2];
    float* out = (float*)d_out;
    (void)in_sizes; (void)n_in; (void)out_size;

    static bool attr_set = false;
    if (!attr_set) {
        cudaFuncSetAttribute(deform_conv_kernel,
                             cudaFuncAttributeMaxDynamicSharedMemorySize,
                             SMEM_FLOATS * (int)sizeof(float));
        attr_set = true;
    }
    deform_conv_kernel<<<Nn * 128, 256, SMEM_FLOATS * sizeof(float)>>>(x, offset, weight, out);
}

// round 14
// speedup vs baseline: 2.0211x; 1.2601x over previous
#include <cuda_runtime.h>
#include <cstdint>

// Problem constants
#define Nn   8
#define Cc   64
#define Hh   128
#define Ww   128
#define Oo   64
#define HW   16384
#define Kk   9
#define CKt  576
#define CHUNK 72          // ck rows per chunk (8 channels x 9 taps)
#define NCH   8           // number of chunks
#define TP    128         // positions per block = one output row
#define WT    68          // transposed w row stride (floats, 16B-aligned)

// dynamic smem layout (floats)
#define SB0   0
#define SB1   (CHUNK*TP)                  // 9216
#define WB0   (2*CHUNK*TP)                // 18432
#define WB1   (2*CHUNK*TP + CHUNK*WT)     // +4896
#define SMEM_FLOATS (2*CHUNK*TP + 2*CHUNK*WT)  // 28224 floats = 112896 B

__device__ __forceinline__ void fma2(unsigned long long &d,
                                     unsigned long long a,
                                     unsigned long long b) {
    asm("fma.rn.f32x2 %0, %1, %2, %0;" : "+l"(d) : "l"(a), "l"(b));
}
__device__ __forceinline__ unsigned long long splat2(float v) {
    unsigned long long r;
    asm("mov.b64 %0, {%1, %2};" : "=l"(r) : "f"(v), "f"(v));
    return r;
}
__device__ __forceinline__ float2 unpack2(unsigned long long v) {
    float2 f;
    asm("mov.b64 {%0, %1}, %2;" : "=f"(f.x), "=f"(f.y) : "l"(v));
    return f;
}

__global__ __launch_bounds__(256, 2)
void deform_conv_kernel(const float* __restrict__ x,
                        const float* __restrict__ offset,
                        const float* __restrict__ weight,
                        float* __restrict__ out)
{
    extern __shared__ float sm[];
    float* const sA = sm + SB0;
    float* const sB = sm + SB1;
    float* const wA = sm + WB0;
    float* const wB = sm + WB1;

    const int tid = threadIdx.x;
    const int b   = blockIdx.x;
    const int n   = b >> 7;          // 128 blocks per image
    const int ho  = b & 127;         // output row
    const int p   = tid & 127;       // this thread's gather column

    // ------------- Phase A: per-thread sampling metadata (registers) -------
    float4   mw[Kk];
    uint32_t mi0[Kk], mi1[Kk];       // packed u16 byte offsets
    #pragma unroll
    for (int k = 0; k < Kk; k++) {
        int kh = k / 3, kw = k - 3 * kh;
        const float* offp = offset + (size_t)(n * 18 + 2 * k) * HW + ho * Ww + p;
        float oy = __ldg(offp);
        float ox = __ldg(offp + HW);
        float py = (float)(ho - 1 + kh) + oy;
        float px = (float)(p  - 1 + kw) + ox;
        py = fminf(fmaxf(py, -16384.f), 16384.f);
        px = fminf(fmaxf(px, -16384.f), 16384.f);
        float y0f = floorf(py), x0f = floorf(px);
        float wy = py - y0f,    wx = px - x0f;
        int y0 = (int)y0f, x0 = (int)x0f;
        int y1 = y0 + 1,   x1 = x0 + 1;
        float vy0 = (y0 >= 0 && y0 < Hh) ? 1.f : 0.f;
        float vy1 = (y1 >= 0 && y1 < Hh) ? 1.f : 0.f;
        float vx0 = (x0 >= 0 && x0 < Ww) ? 1.f : 0.f;
        float vx1 = (x1 >= 0 && x1 < Ww) ? 1.f : 0.f;
        int cy0 = min(max(y0, 0), Hh - 1), cy1 = min(max(y1, 0), Hh - 1);
        int cx0 = min(max(x0, 0), Ww - 1), cx1 = min(max(x1, 0), Ww - 1);
        mw[k] = make_float4((1.f - wy) * (1.f - wx) * vy0 * vx0,
                            (1.f - wy) * wx         * vy0 * vx1,
                            wy         * (1.f - wx) * vy1 * vx0,
                            wy         * wx         * vy1 * vx1);
        uint32_t t00 = (uint32_t)((cy0 * Ww + cx0) << 2);
        uint32_t t01 = (uint32_t)((cy0 * Ww + cx1) << 2);
        uint32_t t10 = (uint32_t)((cy1 * Ww + cx0) << 2);
        uint32_t t11 = (uint32_t)((cy1 * Ww + cx1) << 2);
        mi0[k] = t00 | (t01 << 16);
        mi1[k] = t10 | (t11 << 16);
    }

    const char* const xb = (const char*)(x + (size_t)n * Cc * HW);
    const int half = tid >> 7;       // 0/1: this thread covers 4 channels

    // ------------- gather one chunk (72 rows x 128 p) into sb --------------
    // k-outer (unrolled, meta index compile-time -> registers), c-inner.
    // Row within chunk: j = c_global*9 + k, c_global = half*4 + c.
    auto gather = [&](int cc, float* __restrict__ sb) {
        const char* xpb = xb + ((size_t)(cc * 8 + half * 4) * HW) * 4;
        float* sbp = sb + (half * 36) * TP + p;
        #pragma unroll
        for (int k = 0; k < Kk; k++) {
            const uint32_t i0 = mi0[k], i1 = mi1[k];
            const float4   w  = mw[k];
            #pragma unroll
            for (int c = 0; c < 4; c++) {
                const char* xp = xpb + (size_t)c * (HW * 4);
                float v = w.x * *(const float*)(xp + (i0 & 0xFFFFu))
                        + w.y * *(const float*)(xp + (i0 >> 16))
                        + w.z * *(const float*)(xp + (i1 & 0xFFFFu))
                        + w.w * *(const float*)(xp + (i1 >> 16));
                sbp[(c * 9 + k) * TP] = v;
            }
        }
    };

    // ------------- stage one weight chunk TRANSPOSED: wb[j*WT + o] ---------
    auto stagew = [&](int cc, float* __restrict__ wb) {
        const float* wsrc = weight + cc * CHUNK;
        #pragma unroll
        for (int i = tid; i < Oo * CHUNK; i += 256) {
            int o = i / CHUNK;                 // coalesced read over j
            int j = i - o * CHUNK;
            wb[j * WT + o] = __ldg(wsrc + o * CKt + j);
        }
    };

    // ------------- GEMM: warp owns 8 o (as 4 pairs) x lane 4 p -------------
    const int o0 = (tid >> 5) << 3;     // 0,8,...,56
    const int p0 = (tid & 31) << 2;     // 0..124
    unsigned long long acc[4][4];       // [o-pair q][p idx]
    #pragma unroll
    for (int q = 0; q < 4; q++)
        #pragma unroll
        for (int pp = 0; pp < 4; pp++) acc[q][pp] = 0ull;

    // manually software-pipelined: prefetch j+1 operands before j's FMAs
    auto gemm = [&](const float* __restrict__ sb, const float* __restrict__ wb) {
        const float* sp = sb + p0;
        const float* wp = wb + o0;
        float4     s_c   = *(const float4*)(sp);
        ulonglong2 wlo_c = *(const ulonglong2*)(wp);
        ulonglong2 whi_c = *(const ulonglong2*)(wp + 4);
        #pragma unroll 4
        for (int j = 0; j < CHUNK - 1; j++) {
            float4     s_n   = *(const float4*)(sp + (j + 1) * TP);
            ulonglong2 wlo_n = *(const ulonglong2*)(wp + (j + 1) * WT);
            ulonglong2 whi_n = *(const ulonglong2*)(wp + (j + 1) * WT + 4);
            unsigned long long s0 = splat2(s_c.x), s1 = splat2(s_c.y);
            unsigned long long s2 = splat2(s_c.z), s3 = splat2(s_c.w);
            fma2(acc[0][0], wlo_c.x, s0); fma2(acc[0][1], wlo_c.x, s1);
            fma2(acc[0][2], wlo_c.x, s2); fma2(acc[0][3], wlo_c.x, s3);
            fma2(acc[1][0], wlo_c.y, s0); fma2(acc[1][1], wlo_c.y, s1);
            fma2(acc[1][2], wlo_c.y, s2); fma2(acc[1][3], wlo_c.y, s3);
            fma2(acc[2][0], whi_c.x, s0); fma2(acc[2][1], whi_c.x, s1);
            fma2(acc[2][2], whi_c.x, s2); fma2(acc[2][3], whi_c.x, s3);
            fma2(acc[3][0], whi_c.y, s0); fma2(acc[3][1], whi_c.y, s1);
            fma2(acc[3][2], whi_c.y, s2); fma2(acc[3][3], whi_c.y, s3);
            s_c = s_n; wlo_c = wlo_n; whi_c = whi_n;
        }
        {   // epilogue: j = CHUNK-1
            unsigned long long s0 = splat2(s_c.x), s1 = splat2(s_c.y);
            unsigned long long s2 = splat2(s_c.z), s3 = splat2(s_c.w);
            fma2(acc[0][0], wlo_c.x, s0); fma2(acc[0][1], wlo_c.x, s1);
            fma2(acc[0][2], wlo_c.x, s2); fma2(acc[0][3], wlo_c.x, s3);
            fma2(acc[1][0], wlo_c.y, s0); fma2(acc[1][1], wlo_c.y, s1);
            fma2(acc[1][2], wlo_c.y, s2); fma2(acc[1][3], wlo_c.y, s3);
            fma2(acc[2][0], whi_c.x, s0); fma2(acc[2][1], whi_c.x, s1);
            fma2(acc[2][2], whi_c.x, s2); fma2(acc[2][3], whi_c.x, s3);
            fma2(acc[3][0], whi_c.y, s0); fma2(acc[3][1], whi_c.y, s1);
            fma2(acc[3][2], whi_c.y, s2); fma2(acc[3][3], whi_c.y, s3);
        }
    };

    // ------------- main pipeline: double-buffered chunks -------------------
    stagew(0, wA);
    gather(0, sA);
    __syncthreads();
    #pragma unroll 1
    for (int cc = 0; cc < NCH; cc++) {
        float* scur = (cc & 1) ? sB : sA;
        float* wcur = (cc & 1) ? wB : wA;
        if (cc < NCH - 1) {
            stagew(cc + 1, (cc & 1) ? wA : wB);   // L2-hot LDGs first
            gather(cc + 1, (cc & 1) ? sA : sB);
        }
        gemm(scur, wcur);
        __syncthreads();
    }

    // ------------- epilogue ------------------------------------------------
    // acc[q][pp] = (out[o0+2q][p0+pp], out[o0+2q+1][p0+pp])
    float* ob = out + (size_t)(n * Oo + o0) * HW + ho * Ww + p0;
    #pragma unroll
    for (int q = 0; q < 4; q++) {
        float2 v0 = unpack2(acc[q][0]);
        float2 v1 = unpack2(acc[q][1]);
        float2 v2 = unpack2(acc[q][2]);
        float2 v3 = unpack2(acc[q][3]);
        *(float4*)(ob + (2 * q)     * HW) = make_float4(v0.x, v1.x, v2.x, v3.x);
        *(float4*)(ob + (2 * q + 1) * HW) = make_float4(v0.y, v1.y, v2.y, v3.y);
    }
}

extern "C" void kernel_launch(void* const* d_in, const int* in_sizes, int n_in,
                              void* d_out, int out_size) {
    const float* x      = (const float*)d_in[0];
    const float* offset = (const float*)d_in[1];
    const float* weight = (const float*)d_in[2];
    float* out = (float*)d_out;
    (void)in_sizes; (void)n_in; (void)out_size;

    static bool attr_set = false;
    if (!attr_set) {
        cudaFuncSetAttribute(deform_conv_kernel,
                             cudaFuncAttributeMaxDynamicSharedMemorySize,
                             SMEM_FLOATS * (int)sizeof(float));
        attr_set = true;
    }
    deform_conv_kernel<<<Nn * 128, 256, SMEM_FLOATS * sizeof(float)>>>(x, offset, weight, out);
}

// round 16
// speedup vs baseline: 2.0398x; 1.0093x over previous
#include <cuda_runtime.h>
#include <cstdint>

// Problem constants
#define Nn   8
#define Cc   64
#define Hh   128
#define Ww   128
#define Oo   64
#define HW   16384
#define Kk   9
#define CKt  576
#define CH   64           // chunk rows = channels (one k per chunk)
#define NCH  9
#define TP   128
#define WT   68           // w tile row stride (floats)

// dynamic smem layout (floats)
#define SB0   0
#define SB1   (CH*TP)                    // 8192
#define WB0   (2*CH*TP)                  // 16384
#define WB1   (2*CH*TP + CH*WT)         // 20736
#define MB0f  (2*CH*TP + 2*CH*WT)       // 25088 (16B aligned)
#define SMEM_FLOATS (MB0f + 2*1024)     // 27136 floats = 108544 B

// scratch: x transposed to NHWC, weight transposed to [k][c][o]
__device__ float g_xt[(size_t)Nn * HW * Cc];   // 32 MB
__device__ float g_wt[Kk * Cc * Oo];           // 147 KB

__device__ __forceinline__ void fma2(unsigned long long &d,
                                     unsigned long long a,
                                     unsigned long long b) {
    asm("fma.rn.f32x2 %0, %1, %2, %0;" : "+l"(d) : "l"(a), "l"(b));
}
__device__ __forceinline__ unsigned long long splat2(float v) {
    unsigned long long r;
    asm("mov.b64 %0, {%1, %2};" : "=l"(r) : "f"(v), "f"(v));
    return r;
}
__device__ __forceinline__ float2 unpack2(unsigned long long v) {
    float2 f;
    asm("mov.b64 {%0, %1}, %2;" : "=f"(f.x), "=f"(f.y) : "l"(v));
    return f;
}

// ---- pre-kernel 1: x [N][C][H][W] -> g_xt [N][H*W][C] ----------------------
__global__ __launch_bounds__(256)
void xt_kernel(const float* __restrict__ x) {
    __shared__ float tile[128 * 65];
    const int b    = blockIdx.x;          // 1024 = 8 n * 128 pixel-tiles
    const int n    = b >> 7;
    const int pix0 = (b & 127) << 7;
    const int t    = threadIdx.x;
    const int pix  = t & 127, chh = t >> 7;
    const float* xp = x + (size_t)n * Cc * HW + pix0 + pix;
    #pragma unroll
    for (int i = 0; i < 32; i++) {
        int c = chh * 32 + i;
        tile[pix * 65 + c] = xp[(size_t)c * HW];   // coalesced over pix
    }
    __syncthreads();
    const int c2 = t & 63, pq = t >> 6;
    float* dst = g_xt + ((size_t)n * HW + pix0) * Cc + c2;
    #pragma unroll
    for (int pp = 0; pp < 32; pp++) {
        int px2 = pq * 32 + pp;
        dst[(size_t)px2 * Cc] = tile[px2 * 65 + c2];   // coalesced over c2
    }
}

// ---- pre-kernel 2: weight [O][C][K] -> g_wt [k][c][o] ----------------------
__global__ __launch_bounds__(256)
void wt_kernel(const float* __restrict__ w) {
    int i = blockIdx.x * 256 + threadIdx.x;
    if (i < Kk * Cc * Oo) {
        int k = i / (Cc * Oo);
        int r = i - k * Cc * Oo;
        int c = r >> 6, o = r & 63;
        g_wt[i] = w[o * CKt + c * Kk + k];
    }
}

// ---- main kernel -----------------------------------------------------------
__global__ __launch_bounds__(256, 2)
void deform_conv_kernel(const float* __restrict__ offset,
                        float* __restrict__ out)
{
    extern __shared__ float sm[];
    float* const sA = sm + SB0;
    float* const sB = sm + SB1;
    float* const wA = sm + WB0;
    float* const wB = sm + WB1;

    const int tid  = threadIdx.x;
    const int b    = blockIdx.x;
    const int n    = b >> 7;
    const int ho   = b & 127;
    const int lane = tid & 31;

    // meta buffer q: int4 taps[128] then float4 weights[128] (1024 floats)
    auto mip = [&](int q) { return (int4*)  (sm + MB0f + q * 1024); };
    auto mwp = [&](int q) { return (float4*)(sm + MB0f + q * 1024 + 512); };

    // ------- build sampling metadata for chunk k into buffer q -------------
    auto buildmeta = [&](int k, int q) {
        if (tid < 128) {
            int p  = tid;
            int kh = k / 3, kw = k - 3 * kh;
            const float* offp = offset + (size_t)(n * 18 + 2 * k) * HW + ho * Ww + p;
            float oy = __ldg(offp);
            float ox = __ldg(offp + HW);
            float py = (float)(ho - 1 + kh) + oy;
            float px = (float)(p  - 1 + kw) + ox;
            py = fminf(fmaxf(py, -16384.f), 16384.f);
            px = fminf(fmaxf(px, -16384.f), 16384.f);
            float y0f = floorf(py), x0f = floorf(px);
            float wy = py - y0f,    wx = px - x0f;
            int y0 = (int)y0f, x0 = (int)x0f;
            int y1 = y0 + 1,   x1 = x0 + 1;
            float vy0 = (y0 >= 0 && y0 < Hh) ? 1.f : 0.f;
            float vy1 = (y1 >= 0 && y1 < Hh) ? 1.f : 0.f;
            float vx0 = (x0 >= 0 && x0 < Ww) ? 1.f : 0.f;
            float vx1 = (x1 >= 0 && x1 < Ww) ? 1.f : 0.f;
            int cy0 = min(max(y0, 0), Hh - 1), cy1 = min(max(y1, 0), Hh - 1);
            int cx0 = min(max(x0, 0), Ww - 1), cx1 = min(max(x1, 0), Ww - 1);
            // NHWC byte offsets: pixel index * 256B
            mip(q)[p] = make_int4((cy0 * Ww + cx0) << 8, (cy0 * Ww + cx1) << 8,
                                  (cy1 * Ww + cx0) << 8, (cy1 * Ww + cx1) << 8);
            mwp(q)[p] = make_float4((1.f - wy) * (1.f - wx) * vy0 * vx0,
                                    (1.f - wy) * wx         * vy0 * vx1,
                                    wy         * (1.f - wx) * vy1 * vx0,
                                    wy         * wx         * vy1 * vx1);
        }
    };

    // ------- gather chunk (meta buf q) into sb: warp=16 positions, lane=c --
    const char* const xn = (const char*)g_xt + (size_t)n * HW * Cc * 4;
    auto gather = [&](int q, float* __restrict__ sb) {
        const int4*   mi = mip(q);
        const float4* mw = mwp(q);
        const int pos0 = (tid >> 5) << 4;
        #pragma unroll 4
        for (int pi = 0; pi < 16; pi++) {
            int p = pos0 + pi;
            int4   id = mi[p];            // broadcast
            float4 w  = mw[p];            // broadcast
            #pragma unroll
            for (int h = 0; h < 2; h++) {
                int c = h * 32 + lane;
                const char* xc = xn + c * 4;
                float v = w.x * *(const float*)(xc + id.x)
                        + w.y * *(const float*)(xc + id.y)
                        + w.z * *(const float*)(xc + id.z)
                        + w.w * *(const float*)(xc + id.w);
                sb[c * TP + (p ^ ((c & 31) << 2))] = v;   // swizzled store
            }
        }
    };

    // ------- stage weight chunk k (already [c][o] in g_wt) -----------------
    auto stagew = [&](int k, float* __restrict__ wb) {
        const float* src = g_wt + k * (Cc * Oo);
        #pragma unroll
        for (int i = tid; i < Cc * Oo; i += 256)
            wb[(i >> 6) * WT + (i & 63)] = __ldg(src + i);
    };

    // ------- GEMM: warp owns 8 o (4 pairs) x lane 4 p, sw-pipelined --------
    const int o0 = (tid >> 5) << 3;
    const int p0 = (tid & 31) << 2;
    unsigned long long acc[4][4];
    #pragma unroll
    for (int qq = 0; qq < 4; qq++)
        #pragma unroll
        for (int pp = 0; pp < 4; pp++) acc[qq][pp] = 0ull;

    auto gemm = [&](const float* __restrict__ sb, const float* __restrict__ wb) {
        const float* wp = wb + o0;
        float4     s_c   = *(const float4*)(sb + p0);           // j=0, sj=0
        ulonglong2 wlo_c = *(const ulonglong2*)(wp);
        ulonglong2 whi_c = *(const ulonglong2*)(wp + 4);
        #pragma unroll 4
        for (int j = 0; j < CH - 1; j++) {
            int jn = j + 1;
            float4     s_n   = *(const float4*)(sb + jn * TP + (p0 ^ ((jn & 31) << 2)));
            ulonglong2 wlo_n = *(const ulonglong2*)(wp + jn * WT);
            ulonglong2 whi_n = *(const ulonglong2*)(wp + jn * WT + 4);
            unsigned long long s0 = splat2(s_c.x), s1 = splat2(s_c.y);
            unsigned long long s2 = splat2(s_c.z), s3 = splat2(s_c.w);
            fma2(acc[0][0], wlo_c.x, s0); fma2(acc[0][1], wlo_c.x, s1);
            fma2(acc[0][2], wlo_c.x, s2); fma2(acc[0][3], wlo_c.x, s3);
            fma2(acc[1][0], wlo_c.y, s0); fma2(acc[1][1], wlo_c.y, s1);
            fma2(acc[1][2], wlo_c.y, s2); fma2(acc[1][3], wlo_c.y, s3);
            fma2(acc[2][0], whi_c.x, s0); fma2(acc[2][1], whi_c.x, s1);
            fma2(acc[2][2], whi_c.x, s2); fma2(acc[2][3], whi_c.x, s3);
            fma2(acc[3][0], whi_c.y, s0); fma2(acc[3][1], whi_c.y, s1);
            fma2(acc[3][2], whi_c.y, s2); fma2(acc[3][3], whi_c.y, s3);
            s_c = s_n; wlo_c = wlo_n; whi_c = whi_n;
        }
        {
            unsigned long long s0 = splat2(s_c.x), s1 = splat2(s_c.y);
            unsigned long long s2 = splat2(s_c.z), s3 = splat2(s_c.w);
            fma2(acc[0][0], wlo_c.x, s0); fma2(acc[0][1], wlo_c.x, s1);
            fma2(acc[0][2], wlo_c.x, s2); fma2(acc[0][3], wlo_c.x, s3);
            fma2(acc[1][0], wlo_c.y, s0); fma2(acc[1][1], wlo_c.y, s1);
            fma2(acc[1][2], wlo_c.y, s2); fma2(acc[1][3], wlo_c.y, s3);
            fma2(acc[2][0], whi_c.x, s0); fma2(acc[2][1], whi_c.x, s1);
            fma2(acc[2][2], whi_c.x, s2); fma2(acc[2][3], whi_c.x, s3);
            fma2(acc[3][0], whi_c.y, s0); fma2(acc[3][1], whi_c.y, s1);
            fma2(acc[3][2], whi_c.y, s2); fma2(acc[3][3], whi_c.y, s3);
        }
    };

    // ------- pipeline: meta 2 ahead, data 1 ahead --------------------------
    buildmeta(0, 0);
    __syncthreads();
    stagew(0, wA);
    gather(0, sA);
    buildmeta(1, 1);
    __syncthreads();
    #pragma unroll 1
    for (int cc = 0; cc < NCH; cc++) {
        float* scur = (cc & 1) ? sB : sA;
        float* wcur = (cc & 1) ? wB : wA;
        if (cc < NCH - 1) {
            stagew(cc + 1, (cc & 1) ? wA : wB);
            gather((cc + 1) & 1, (cc & 1) ? sA : sB);
            if (cc + 2 < NCH) buildmeta(cc + 2, cc & 1);
        }
        gemm(scur, wcur);
        __syncthreads();
    }

    // ------- epilogue ------------------------------------------------------
    float* ob = out + (size_t)(n * Oo + o0) * HW + ho * Ww + p0;
    #pragma unroll
    for (int q = 0; q < 4; q++) {
        float2 v0 = unpack2(acc[q][0]);
        float2 v1 = unpack2(acc[q][1]);
        float2 v2 = unpack2(acc[q][2]);
        float2 v3 = unpack2(acc[q][3]);
        *(float4*)(ob + (2 * q)     * HW) = make_float4(v0.x, v1.x, v2.x, v3.x);
        *(float4*)(ob + (2 * q + 1) * HW) = make_float4(v0.y, v1.y, v2.y, v3.y);
    }
}

extern "C" void kernel_launch(void* const* d_in, const int* in_sizes, int n_in,
                              void* d_out, int out_size) {
    const float* x      = (const float*)d_in[0];
    const float* offset = (const float*)d_in[1];
    const float* weight = (const float*)d_in[2];
    float* out = (float*)d_out;
    (void)in_sizes; (void)n_in; (void)out_size;

    static bool attr_set = false;
    if (!attr_set) {
        cudaFuncSetAttribute(deform_conv_kernel,
                             cudaFuncAttributeMaxDynamicSharedMemorySize,
                             SMEM_FLOATS * (int)sizeof(float));
        attr_set = true;
    }
    xt_kernel<<<Nn * 128, 256>>>(x);
    wt_kernel<<<(Kk * Cc * Oo + 255) / 256, 256>>>(weight);
    deform_conv_kernel<<<Nn * 128, 256, SMEM_FLOATS * sizeof(float)>>>(offset, out);
}